// round 13
// baseline (speedup 1.0000x reference)
#include <cuda_runtime.h>
#include <cuda_bf16.h>
#include <cstdint>

#define EDIM 1024
#define HD_  64
#define HH_  16
#define TT_  1024
#define BB_  2
#define LL_  4
#define FF_  4096
#define VV_  32000
#define MROWS (BB_*TT_)   // 2048
#define BHN  (BB_*HH_)    // 32

// ---------------- scratch (static device memory; no allocs) ----------------
__device__ float g_x   [MROWS*EDIM];
__device__ float g_z   [MROWS*EDIM];
__device__ float g_z2  [MROWS*EDIM];
__device__ float g_q   [MROWS*EDIM];
__device__ float g_k   [MROWS*EDIM];
__device__ float g_v   [MROWS*EDIM];
__device__ int   g_tok64;

// bf16 hi/lo activation buffers
__device__ __nv_bfloat16 g_Ah[MROWS*EDIM], g_Al[MROWS*EDIM];   // E-wide acts
__device__ __nv_bfloat16 g_Hh[MROWS*FF_],  g_Hl[MROWS*FF_];    // FF-wide acts
// bf16 hi/lo weights in ORIGINAL [K,N] layout (no transpose)
__device__ __nv_bfloat16 g_Wqh[LL_*EDIM*EDIM], g_Wql[LL_*EDIM*EDIM];
__device__ __nv_bfloat16 g_Wkh[LL_*EDIM*EDIM], g_Wkl[LL_*EDIM*EDIM];
__device__ __nv_bfloat16 g_Wvh[LL_*EDIM*EDIM], g_Wvl[LL_*EDIM*EDIM];
__device__ __nv_bfloat16 g_Woh[LL_*EDIM*EDIM], g_Wol[LL_*EDIM*EDIM];
__device__ __nv_bfloat16 g_W1h[LL_*EDIM*FF_],  g_W1l[LL_*EDIM*FF_];
__device__ __nv_bfloat16 g_W2h[LL_*EDIM*FF_],  g_W2l[LL_*EDIM*FF_];
__device__ __nv_bfloat16 g_Whh[EDIM*VV_],      g_Whl[EDIM*VV_];

// ---------------- PTX helpers (family-safe) ----------------
__device__ __forceinline__ uint32_t smem_u32(const void* p) {
    uint32_t a;
    asm("{ .reg .u64 t; cvta.to.shared.u64 t, %1; cvt.u32.u64 %0, t; }" : "=r"(a) : "l"(p));
    return a;
}
__device__ __forceinline__ void ldsm_x4(uint32_t* r, uint32_t addr) {
    asm volatile("ldmatrix.sync.aligned.m8n8.x4.shared.b16 {%0,%1,%2,%3}, [%4];"
                 : "=r"(r[0]), "=r"(r[1]), "=r"(r[2]), "=r"(r[3]) : "r"(addr));
}
__device__ __forceinline__ void ldsm_x4_t(uint32_t* r, uint32_t addr) {
    asm volatile("ldmatrix.sync.aligned.m8n8.x4.trans.shared.b16 {%0,%1,%2,%3}, [%4];"
                 : "=r"(r[0]), "=r"(r[1]), "=r"(r[2]), "=r"(r[3]) : "r"(addr));
}
__device__ __forceinline__ void mma16816(float* d, const uint32_t* a, const uint32_t* b) {
    asm volatile("mma.sync.aligned.m16n8k16.row.col.f32.bf16.bf16.f32 "
                 "{%0,%1,%2,%3}, {%4,%5,%6,%7}, {%8,%9}, {%0,%1,%2,%3};"
                 : "+f"(d[0]), "+f"(d[1]), "+f"(d[2]), "+f"(d[3])
                 : "r"(a[0]), "r"(a[1]), "r"(a[2]), "r"(a[3]), "r"(b[0]), "r"(b[1]));
}
#define CP_ASYNC16(dst, src) \
    asm volatile("cp.async.cg.shared.global [%0], [%1], 16;" :: "r"(dst), "l"(src))
#define CP_COMMIT() asm volatile("cp.async.commit_group;" ::: "memory")
#define CP_WAIT(n)  asm volatile("cp.async.wait_group %0;" :: "n"(n) : "memory")

__device__ __forceinline__ __nv_bfloat162 split_hi2(float a, float b) {
    __nv_bfloat162 r; r.x = __float2bfloat16(a); r.y = __float2bfloat16(b); return r;
}
__device__ __forceinline__ __nv_bfloat162 split_lo2(float a, float b,
                                                    __nv_bfloat162 h) {
    __nv_bfloat162 r;
    r.x = __float2bfloat16(a - __bfloat162float(h.x));
    r.y = __float2bfloat16(b - __bfloat162float(h.y));
    return r;
}

// ---------------- reductions ----------------
__device__ __forceinline__ float blockReduceSum(float v, float* sh) {
    __syncthreads();
    #pragma unroll
    for (int o = 16; o; o >>= 1) v += __shfl_xor_sync(0xffffffffu, v, o);
    if ((threadIdx.x & 31) == 0) sh[threadIdx.x >> 5] = v;
    __syncthreads();
    int nw = blockDim.x >> 5;
    float t = (threadIdx.x < (unsigned)nw) ? sh[threadIdx.x] : 0.f;
    if (threadIdx.x < 32) {
        #pragma unroll
        for (int o = 16; o; o >>= 1) t += __shfl_xor_sync(0xffffffffu, t, o);
        if (threadIdx.x == 0) sh[0] = t;
    }
    __syncthreads();
    return sh[0];
}

// ---------------- token dtype detect ----------------
__global__ void detect_kernel(const int* __restrict__ tok) {
    __shared__ int nz;
    if (threadIdx.x == 0) nz = 0;
    __syncthreads();
    int c = 0;
    for (int j = threadIdx.x; j < 1024; j += blockDim.x)
        if (tok[2*j + 1] != 0) c++;
    if (c) atomicAdd(&nz, c);
    __syncthreads();
    if (threadIdx.x == 0) g_tok64 = (nz == 0) ? 1 : 0;
}

// ---------------- embedding + positional encoding ----------------
__global__ __launch_bounds__(256) void embed_kernel(const void* __restrict__ tokp,
                                                    const float* __restrict__ emb,
                                                    float* __restrict__ X) {
    int row = blockIdx.x;
    int t   = row & (TT_ - 1);
    int token;
    if (g_tok64) token = (int)((const long long*)tokp)[row];
    else         token = ((const int*)tokp)[row];
    int e = threadIdx.x * 4;
    float4 v = *(const float4*)(emb + (size_t)token * EDIM + e);
    double i0 = (double)(e >> 1);
    double i1 = i0 + 1.0;
    double d0 = pow(10000.0, 2.0 * i0 / (double)EDIM);
    double d1 = pow(10000.0, 2.0 * i1 / (double)EDIM);
    double a0 = (double)t / d0;
    double a1 = (double)t / d1;
    v.x += (float)sin(a0); v.y += (float)cos(a0);
    v.z += (float)sin(a1); v.w += (float)cos(a1);
    *(float4*)(X + (size_t)row * EDIM + e) = v;
}

// ---------------- layernorm + bf16 split emit ----------------
__global__ __launch_bounds__(256) void ln_kernel(const float* __restrict__ X,
                                                 const float* __restrict__ g,
                                                 const float* __restrict__ b,
                                                 float* __restrict__ Y,
                                                 __nv_bfloat16* __restrict__ Oh,
                                                 __nv_bfloat16* __restrict__ Ol) {
    __shared__ float sh[32];
    int row = blockIdx.x;
    int e = threadIdx.x * 4;
    const float* xr = X + (size_t)row * EDIM;
    float4 v = *(const float4*)(xr + e);
    float mean = blockReduceSum(v.x + v.y + v.z + v.w, sh) * (1.f / EDIM);
    float dx = v.x - mean, dy = v.y - mean, dz = v.z - mean, dw = v.w - mean;
    float var = blockReduceSum(dx*dx + dy*dy + dz*dz + dw*dw, sh) * (1.f / EDIM);
    float r = rsqrtf(var + 1e-5f);
    float4 gg = *(const float4*)(g + e);
    float4 bb = *(const float4*)(b + e);
    float4 o;
    o.x = dx * r * gg.x + bb.x;
    o.y = dy * r * gg.y + bb.y;
    o.z = dz * r * gg.z + bb.z;
    o.w = dw * r * gg.w + bb.w;
    size_t base = (size_t)row * EDIM + e;
    *(float4*)(Y + base) = o;
    __nv_bfloat162 h0 = split_hi2(o.x, o.y), h1 = split_hi2(o.z, o.w);
    *(__nv_bfloat162*)(Oh + base)     = h0;
    *(__nv_bfloat162*)(Oh + base + 2) = h1;
    *(__nv_bfloat162*)(Ol + base)     = split_lo2(o.x, o.y, h0);
    *(__nv_bfloat162*)(Ol + base + 2) = split_lo2(o.z, o.w, h1);
}

// ---------------- fp32 -> bf16 hi/lo streaming split, 8 elems/thread --------
__global__ __launch_bounds__(256) void cvt_w_kernel(const float* __restrict__ W,
                                                    __nv_bfloat16* __restrict__ H,
                                                    __nv_bfloat16* __restrict__ Lo) {
    size_t i = ((size_t)blockIdx.x * 256 + threadIdx.x) * 8;
    float4 a0 = *(const float4*)(W + i);
    float4 a1 = *(const float4*)(W + i + 4);
    __nv_bfloat162 hb[4], lb[4];
    hb[0] = split_hi2(a0.x, a0.y); hb[1] = split_hi2(a0.z, a0.w);
    hb[2] = split_hi2(a1.x, a1.y); hb[3] = split_hi2(a1.z, a1.w);
    lb[0] = split_lo2(a0.x, a0.y, hb[0]); lb[1] = split_lo2(a0.z, a0.w, hb[1]);
    lb[2] = split_lo2(a1.x, a1.y, hb[2]); lb[3] = split_lo2(a1.z, a1.w, hb[3]);
    *(uint4*)(H + i)  = *(uint4*)hb;
    *(uint4*)(Lo + i) = *(uint4*)lb;
}

// ---------------- bf16 hi/lo tensor-core GEMM (mma.sync, warp 64x64) --------
// C[M,N] = A[M,K] @ B[K,N] ; fp32 accum of hh + hl + lh.
// A row-major [M,K]; B row-major [K,N] (ldmatrix.trans).
// CTA tile 128x128, 4 warps (128 thr) in 2x2, warp tile 64x64, K chunk 32,
// 2-stage cp.async. 75776 B smem, 2 CTAs/SM (256 thr -> 256 regs/thread).
// MMA terms separated into 3 passes -> acc reuse distance 32 (no RAW chains).
#define ASTRIDE 40
#define BSTRIDE 136
#define A_TILE (128 * ASTRIDE)                // 5120 bf16
#define B_TILE (32 * BSTRIDE)                 // 4352 bf16
#define STAGE_ELEMS (2 * A_TILE + 2 * B_TILE) // 18944 bf16
#define NSTAGE 2
#define GEMM_SMEM (NSTAGE * STAGE_ELEMS * 2)  // 75776 B

__global__ __launch_bounds__(128, 2) void gemm_kernel(
    const __nv_bfloat16* __restrict__ Ah, const __nv_bfloat16* __restrict__ Al,
    const __nv_bfloat16* __restrict__ Bh0, const __nv_bfloat16* __restrict__ Bl0,
    const __nv_bfloat16* __restrict__ Bh1, const __nv_bfloat16* __restrict__ Bl1,
    const __nv_bfloat16* __restrict__ Bh2, const __nv_bfloat16* __restrict__ Bl2,
    float* __restrict__ C0, float* __restrict__ C1, float* __restrict__ C2,
    __nv_bfloat16* __restrict__ Oh, __nv_bfloat16* __restrict__ Ol,
    const float* __restrict__ bias, const float* __restrict__ res,
    int K, int N, int relu)
{
    extern __shared__ __nv_bfloat16 smem[];
    const int tid = threadIdx.x;
    const int lane = tid & 31, wid = tid >> 5;   // wid 0..3
    const int wm = wid & 1, wn = wid >> 1;       // 2x2 warp grid
    const int bm = blockIdx.x * 128, bn = blockIdx.y * 128;
    const int z = blockIdx.z;
    const __nv_bfloat16* Bh = (z == 0) ? Bh0 : (z == 1) ? Bh1 : Bh2;
    const __nv_bfloat16* Bl = (z == 0) ? Bl0 : (z == 1) ? Bl1 : Bl2;
    float* C = (z == 0) ? C0 : (z == 1) ? C1 : C2;

    const uint32_t sb = smem_u32(smem);
    const int nc = K >> 5;

    auto load_stage = [&](int st, int kc) {
        uint32_t base = sb + (uint32_t)(st * STAGE_ELEMS * 2);
        // A tiles: 512 chunks each, 4 per thread (id = tid + 128*r)
        #pragma unroll
        for (int t4 = 0; t4 < 2; t4++) {
            const __nv_bfloat16* src = t4 ? Al : Ah;
            uint32_t dstb = base + (uint32_t)(t4 * A_TILE * 2);
            #pragma unroll
            for (int r = 0; r < 4; r++) {
                int id = tid + r * 128;
                int row = id >> 2, cc = (id & 3) * 8;
                CP_ASYNC16(dstb + (row * ASTRIDE + cc) * 2,
                           src + (size_t)(bm + row) * K + kc * 32 + cc);
            }
        }
        // B tiles: 512 chunks each
        #pragma unroll
        for (int t4 = 0; t4 < 2; t4++) {
            const __nv_bfloat16* src = t4 ? Bl : Bh;
            uint32_t dstb = base + (uint32_t)((2 * A_TILE + t4 * B_TILE) * 2);
            #pragma unroll
            for (int r = 0; r < 4; r++) {
                int id = tid + r * 128;
                int row = id >> 4, cc = (id & 15) * 8;
                CP_ASYNC16(dstb + (row * BSTRIDE + cc) * 2,
                           src + (size_t)(kc * 32 + row) * N + bn + cc);
            }
        }
    };

    float acc[4][8][4];
    #pragma unroll
    for (int i = 0; i < 4; i++)
        #pragma unroll
        for (int j = 0; j < 8; j++)
            #pragma unroll
            for (int r = 0; r < 4; r++) acc[i][j][r] = 0.f;

    load_stage(0, 0); CP_COMMIT();

    const int a_lrow = lane & 15;
    const int a_lcol = (lane & 16) ? 8 : 0;
    const int bt_row = lane & 15;
    const int bt_col = (lane >> 4) * 8;

    for (int c = 0; c < nc; c++) {
        CP_WAIT(0);
        __syncthreads();
        // Slot (c+1)&1 was last READ in iter c-1; all threads past this
        // barrier, so writing it now is race-free.
        if (c + 1 < nc) { load_stage((c + 1) & 1, c + 1); CP_COMMIT(); }

        const uint32_t stb = sb + (uint32_t)(((c & 1) * STAGE_ELEMS) * 2);
        const uint32_t pAh = stb;
        const uint32_t pAl = stb + A_TILE * 2;
        const uint32_t pBh = stb + 2 * A_TILE * 2;
        const uint32_t pBl = pBh + B_TILE * 2;

        #pragma unroll
        for (int ks = 0; ks < 2; ks++) {
            const int k0 = ks * 16;
            uint32_t ah[4][4], al[4][4];
            #pragma unroll
            for (int mf = 0; mf < 4; mf++) {
                int row = wm * 64 + mf * 16 + a_lrow;
                uint32_t off = (uint32_t)((row * ASTRIDE + k0 + a_lcol) * 2);
                ldsm_x4(ah[mf], pAh + off);
                ldsm_x4(al[mf], pAl + off);
            }
            uint32_t bh[4][4], bl[4][4];
            #pragma unroll
            for (int np = 0; np < 4; np++) {
                uint32_t off = (uint32_t)(((k0 + bt_row) * BSTRIDE
                                + wn * 64 + np * 16 + bt_col) * 2);
                ldsm_x4_t(bh[np], pBh + off);
                ldsm_x4_t(bl[np], pBl + off);
            }
            // pass 1: hh (acc element order hh -> hl -> lh preserved)
            #pragma unroll
            for (int mf = 0; mf < 4; mf++)
                #pragma unroll
                for (int np = 0; np < 4; np++)
                    #pragma unroll
                    for (int sub = 0; sub < 2; sub++)
                        mma16816(acc[mf][np * 2 + sub], ah[mf], &bh[np][2 * sub]);
            // pass 2: hl
            #pragma unroll
            for (int mf = 0; mf < 4; mf++)
                #pragma unroll
                for (int np = 0; np < 4; np++)
                    #pragma unroll
                    for (int sub = 0; sub < 2; sub++)
                        mma16816(acc[mf][np * 2 + sub], ah[mf], &bl[np][2 * sub]);
            // pass 3: lh
            #pragma unroll
            for (int mf = 0; mf < 4; mf++)
                #pragma unroll
                for (int np = 0; np < 4; np++)
                    #pragma unroll
                    for (int sub = 0; sub < 2; sub++)
                        mma16816(acc[mf][np * 2 + sub], al[mf], &bh[np][2 * sub]);
        }
    }
    __syncthreads();

    // epilogue
    #pragma unroll
    for (int mf = 0; mf < 4; mf++) {
        int row0 = bm + wm * 64 + mf * 16 + (lane >> 2);
        #pragma unroll
        for (int nf = 0; nf < 8; nf++) {
            int col = bn + wn * 64 + nf * 8 + (lane & 3) * 2;
            float2 bv = bias ? *(const float2*)(bias + col) : make_float2(0.f, 0.f);
            #pragma unroll
            for (int half = 0; half < 2; half++) {
                int row = row0 + half * 8;
                float v0 = acc[mf][nf][half * 2 + 0] + bv.x;
                float v1 = acc[mf][nf][half * 2 + 1] + bv.y;
                if (res) {
                    float2 rv = *(const float2*)(res + (size_t)row * N + col);
                    v0 += rv.x; v1 += rv.y;
                }
                if (relu) { v0 = fmaxf(v0, 0.f); v1 = fmaxf(v1, 0.f); }
                if (Oh) {
                    __nv_bfloat162 h = split_hi2(v0, v1);
                    *(__nv_bfloat162*)(Oh + (size_t)row * N + col) = h;
                    *(__nv_bfloat162*)(Ol + (size_t)row * N + col) = split_lo2(v0, v1, h);
                } else {
                    *(float2*)(C + (size_t)row * N + col) = make_float2(v0, v1);
                }
            }
        }
    }
}

// ---------------- fused flash attention (fp32 compute, bf16 split out) ------
#define FL_STRIDE 68
#define FL_SMEM   (3 * 64 * FL_STRIDE * 4)

__global__ __launch_bounds__(256) void flash_kernel(const float* __restrict__ Q,
                                                    const float* __restrict__ Km,
                                                    const float* __restrict__ V,
                                                    __nv_bfloat16* __restrict__ Oh,
                                                    __nv_bfloat16* __restrict__ Ol) {
    extern __shared__ float smf[];
    float (*Ks)[FL_STRIDE] = (float(*)[FL_STRIDE])smf;
    float (*Vs)[FL_STRIDE] = (float(*)[FL_STRIDE])(smf + 64 * FL_STRIDE);
    float (*QP)[FL_STRIDE] = (float(*)[FL_STRIDE])(smf + 2 * 64 * FL_STRIDE);

    const int bt = blockIdx.x;
    const int bh = blockIdx.y, b = bh / HH_, h = bh % HH_;
    const int tx = threadIdx.x, ty = threadIdx.y;
    const int tid = ty * 16 + tx;
    const int lr = tid >> 4;
    const int d4 = (tid & 15) * 4;

    #pragma unroll
    for (int rr = 0; rr < 4; rr++) {
        int r = lr + rr * 16;
        float4 kv = *(const float4*)(Km + (size_t)(b*TT_ + bt*64 + r) * EDIM + h*HD_ + d4);
        Ks[d4+0][r] = kv.x; Ks[d4+1][r] = kv.y; Ks[d4+2][r] = kv.z; Ks[d4+3][r] = kv.w;
    }

    float acc[4][4] = {};
    float m[4], l[4];
    #pragma unroll
    for (int i = 0; i < 4; i++) { m[i] = -1e30f; l[i] = 0.f; }
    const float scale = 0.125f;

    for (int st = 0; st <= bt; st++) {
        __syncthreads();
        #pragma unroll
        for (int rr = 0; rr < 4; rr++) {
            int r = lr + rr * 16;
            float4 qv = *(const float4*)(Q + (size_t)(b*TT_ + st*64 + r) * EDIM + h*HD_ + d4);
            QP[d4+0][r] = qv.x; QP[d4+1][r] = qv.y; QP[d4+2][r] = qv.z; QP[d4+3][r] = qv.w;
            float4 vv = *(const float4*)(V + (size_t)(b*TT_ + st*64 + r) * EDIM + h*HD_ + d4);
            *(float4*)&Vs[r][d4] = vv;
        }
        __syncthreads();

        float s4[4][4] = {};
        #pragma unroll
        for (int d = 0; d < 64; d++) {
            float4 a = *(float4*)&Ks[d][ty * 4];
            float4 q = *(float4*)&QP[d][tx * 4];
            float ar[4] = {a.x, a.y, a.z, a.w};
            float qr[4] = {q.x, q.y, q.z, q.w};
            #pragma unroll
            for (int i = 0; i < 4; i++)
                #pragma unroll
                for (int j = 0; j < 4; j++) s4[i][j] += ar[i] * qr[j];
        }
        if (st == bt) {
            #pragma unroll
            for (int i = 0; i < 4; i++)
                #pragma unroll
                for (int j = 0; j < 4; j++)
                    s4[i][j] = (tx*4+j <= ty*4+i) ? s4[i][j] * scale : -1e30f;
        } else {
            #pragma unroll
            for (int i = 0; i < 4; i++)
                #pragma unroll
                for (int j = 0; j < 4; j++) s4[i][j] *= scale;
        }

        __syncthreads();

        #pragma unroll
        for (int i = 0; i < 4; i++) {
            float mx = fmaxf(fmaxf(s4[i][0], s4[i][1]), fmaxf(s4[i][2], s4[i][3]));
            #pragma unroll
            for (int o = 8; o; o >>= 1) mx = fmaxf(mx, __shfl_xor_sync(0xffffffffu, mx, o, 16));
            float mn = fmaxf(m[i], mx);
            float alpha = __expf(m[i] - mn);
            float p0 = __expf(s4[i][0] - mn);
            float p1 = __expf(s4[i][1] - mn);
            float p2 = __expf(s4[i][2] - mn);
            float p3 = __expf(s4[i][3] - mn);
            float rs = p0 + p1 + p2 + p3;
            #pragma unroll
            for (int o = 8; o; o >>= 1) rs += __shfl_xor_sync(0xffffffffu, rs, o, 16);
            l[i] = l[i] * alpha + rs;
            m[i] = mn;
            #pragma unroll
            for (int j = 0; j < 4; j++) acc[i][j] *= alpha;
            QP[tx*4+0][ty*4+i] = p0;
            QP[tx*4+1][ty*4+i] = p1;
            QP[tx*4+2][ty*4+i] = p2;
            QP[tx*4+3][ty*4+i] = p3;
        }
        __syncthreads();

        #pragma unroll
        for (int s = 0; s < 64; s++) {
            float4 pv = *(float4*)&QP[s][ty * 4];
            float4 vv = *(float4*)&Vs[s][tx * 4];
            float pr[4] = {pv.x, pv.y, pv.z, pv.w};
            float vr[4] = {vv.x, vv.y, vv.z, vv.w};
            #pragma unroll
            for (int i = 0; i < 4; i++)
                #pragma unroll
                for (int j = 0; j < 4; j++) acc[i][j] += pr[i] * vr[j];
        }
    }

    #pragma unroll
    for (int i = 0; i < 4; i++) {
        float inv = 1.f / l[i];
        int tg = bt * 64 + ty * 4 + i;
        size_t base = (size_t)(b*TT_ + tg) * EDIM + h*HD_ + tx*4;
        float v0 = acc[i][0] * inv, v1 = acc[i][1] * inv;
        float v2 = acc[i][2] * inv, v3 = acc[i][3] * inv;
        __nv_bfloat162 h0 = split_hi2(v0, v1), h1 = split_hi2(v2, v3);
        *(__nv_bfloat162*)(Oh + base)     = h0;
        *(__nv_bfloat162*)(Oh + base + 2) = h1;
        *(__nv_bfloat162*)(Ol + base)     = split_lo2(v0, v1, h0);
        *(__nv_bfloat162*)(Ol + base + 2) = split_lo2(v2, v3, h1);
    }
}

// ---------------- host driver ----------------
template <typename T>
static T* symAddr(const void* sym) {
    void* p = nullptr;
    cudaGetSymbolAddress(&p, sym);
    return (T*)p;
}

extern "C" void kernel_launch(void* const* d_in, const int* in_sizes, int n_in,
                              void* d_out, int out_size) {
    const void*  tokens = d_in[0];
    const float* emb    = (const float*)d_in[1];
    const float* Wq     = (const float*)d_in[2];
    const float* Wk     = (const float*)d_in[3];
    const float* Wv     = (const float*)d_in[4];
    const float* Wo     = (const float*)d_in[5];
    const float* bo     = (const float*)d_in[6];
    const float* ln1_g  = (const float*)d_in[7];
    const float* ln1_b  = (const float*)d_in[8];
    const float* ln2_g  = (const float*)d_in[9];
    const float* ln2_b  = (const float*)d_in[10];
    const float* W1     = (const float*)d_in[11];
    const float* b1     = (const float*)d_in[12];
    const float* W2     = (const float*)d_in[13];
    const float* b2     = (const float*)d_in[14];
    const float* lnf_g  = (const float*)d_in[15];
    const float* lnf_b  = (const float*)d_in[16];
    const float* Wh     = (const float*)d_in[17];
    const float* bh     = (const float*)d_in[18];

    float* px  = symAddr<float>(g_x);
    float* pz  = symAddr<float>(g_z);
    float* pz2 = symAddr<float>(g_z2);
    float* pq  = symAddr<float>(g_q);
    float* pk  = symAddr<float>(g_k);
    float* pv  = symAddr<float>(g_v);
    __nv_bfloat16* pAh = symAddr<__nv_bfloat16>(g_Ah);
    __nv_bfloat16* pAl = symAddr<__nv_bfloat16>(g_Al);
    __nv_bfloat16* pHh = symAddr<__nv_bfloat16>(g_Hh);
    __nv_bfloat16* pHl = symAddr<__nv_bfloat16>(g_Hl);
    __nv_bfloat16* pWqh = symAddr<__nv_bfloat16>(g_Wqh), *pWql = symAddr<__nv_bfloat16>(g_Wql);
    __nv_bfloat16* pWkh = symAddr<__nv_bfloat16>(g_Wkh), *pWkl = symAddr<__nv_bfloat16>(g_Wkl);
    __nv_bfloat16* pWvh = symAddr<__nv_bfloat16>(g_Wvh), *pWvl = symAddr<__nv_bfloat16>(g_Wvl);
    __nv_bfloat16* pWoh = symAddr<__nv_bfloat16>(g_Woh), *pWol = symAddr<__nv_bfloat16>(g_Wol);
    __nv_bfloat16* pW1h = symAddr<__nv_bfloat16>(g_W1h), *pW1l = symAddr<__nv_bfloat16>(g_W1l);
    __nv_bfloat16* pW2h = symAddr<__nv_bfloat16>(g_W2h), *pW2l = symAddr<__nv_bfloat16>(g_W2l);
    __nv_bfloat16* pWhh = symAddr<__nv_bfloat16>(g_Whh), *pWhl = symAddr<__nv_bfloat16>(g_Whl);

    cudaFuncSetAttribute(flash_kernel, cudaFuncAttributeMaxDynamicSharedMemorySize, FL_SMEM);
    cudaFuncSetAttribute(gemm_kernel,  cudaFuncAttributeMaxDynamicSharedMemorySize, GEMM_SMEM);

    const size_t EE = (size_t)EDIM * EDIM;
    const size_t EF = (size_t)EDIM * FF_;

    // ---- weight conversion: 7 batched launches over full [L,...] tensors ---
    cvt_w_kernel<<<(int)(LL_*EE / 2048), 256>>>(Wq, pWqh, pWql);
    cvt_w_kernel<<<(int)(LL_*EE / 2048), 256>>>(Wk, pWkh, pWkl);
    cvt_w_kernel<<<(int)(LL_*EE / 2048), 256>>>(Wv, pWvh, pWvl);
    cvt_w_kernel<<<(int)(LL_*EE / 2048), 256>>>(Wo, pWoh, pWol);
    cvt_w_kernel<<<(int)(LL_*EF / 2048), 256>>>(W1, pW1h, pW1l);
    cvt_w_kernel<<<(int)(LL_*EF / 2048), 256>>>(W2, pW2h, pW2l);
    cvt_w_kernel<<<(int)((size_t)EDIM * VV_ / 2048), 256>>>(Wh, pWhh, pWhl);

    detect_kernel<<<1, 256>>>((const int*)tokens);
    embed_kernel<<<MROWS, 256>>>(tokens, emb, px);

    // grids: x = M tiles (fastest) for L2 B-reuse
    dim3 gQKV(MROWS/128, EDIM/128, 3);
    dim3 gEE(MROWS/128, EDIM/128, 1);
    dim3 gEF(MROWS/128, FF_/128, 1);
    dim3 gEV(MROWS/128, VV_/128, 1);
    dim3 thr2(16, 16);

    for (int l = 0; l < LL_; l++) {
        ln_kernel<<<MROWS, 256>>>(px, ln1_g + l*EDIM, ln1_b + l*EDIM, pz, pAh, pAl);
        gemm_kernel<<<gQKV, 128, GEMM_SMEM>>>(pAh, pAl,
            pWqh + l*EE, pWql + l*EE, pWkh + l*EE, pWkl + l*EE, pWvh + l*EE, pWvl + l*EE,
            pq, pk, pv, nullptr, nullptr, nullptr, nullptr, EDIM, EDIM, 0);
        flash_kernel<<<dim3(TT_/64, BHN), thr2, FL_SMEM>>>(pq, pk, pv, pAh, pAl);
        gemm_kernel<<<gEE, 128, GEMM_SMEM>>>(pAh, pAl,
            pWoh + l*EE, pWol + l*EE, nullptr, nullptr, nullptr, nullptr,
            pz, nullptr, nullptr, nullptr, nullptr, bo + l*EDIM, pz, EDIM, EDIM, 0);
        ln_kernel<<<MROWS, 256>>>(pz, ln2_g + l*EDIM, ln2_b + l*EDIM, pz2, pAh, pAl);
        gemm_kernel<<<gEF, 128, GEMM_SMEM>>>(pAh, pAl,
            pW1h + l*EF, pW1l + l*EF, nullptr, nullptr, nullptr, nullptr,
            nullptr, nullptr, nullptr, pHh, pHl, b1 + l*FF_, nullptr, EDIM, FF_, 1);
        gemm_kernel<<<gEE, 128, GEMM_SMEM>>>(pHh, pHl,
            pW2h + l*EF, pW2l + l*EF, nullptr, nullptr, nullptr, nullptr,
            px, nullptr, nullptr, nullptr, nullptr, b2 + l*EDIM, pz2, FF_, EDIM, 0);
    }
    ln_kernel<<<MROWS, 256>>>(px, lnf_g, lnf_b, pz, pAh, pAl);
    gemm_kernel<<<gEV, 128, GEMM_SMEM>>>(pAh, pAl,
        pWhh, pWhl, nullptr, nullptr, nullptr, nullptr,
        (float*)d_out, nullptr, nullptr, nullptr, nullptr, bh, nullptr, EDIM, VV_, 0);
}

// round 16
// speedup vs baseline: 1.5517x; 1.5517x over previous
#include <cuda_runtime.h>
#include <cuda_bf16.h>
#include <cstdint>

#define EDIM 1024
#define HD_  64
#define HH_  16
#define TT_  1024
#define BB_  2
#define LL_  4
#define FF_  4096
#define VV_  32000
#define MROWS (BB_*TT_)   // 2048
#define BHN  (BB_*HH_)    // 32

// ---------------- scratch (static device memory; no allocs) ----------------
__device__ float g_x   [MROWS*EDIM];
__device__ float g_z   [MROWS*EDIM];
__device__ float g_z2  [MROWS*EDIM];
__device__ float g_q   [MROWS*EDIM];
__device__ float g_k   [MROWS*EDIM];
__device__ float g_v   [MROWS*EDIM];
__device__ int   g_tok64;

// bf16 hi/lo activation buffers
__device__ __nv_bfloat16 g_Ah[MROWS*EDIM], g_Al[MROWS*EDIM];   // E-wide acts
__device__ __nv_bfloat16 g_Hh[MROWS*FF_],  g_Hl[MROWS*FF_];    // FF-wide acts
// bf16 hi/lo weights in ORIGINAL [K,N] layout (no transpose)
__device__ __nv_bfloat16 g_Wqh[LL_*EDIM*EDIM], g_Wql[LL_*EDIM*EDIM];
__device__ __nv_bfloat16 g_Wkh[LL_*EDIM*EDIM], g_Wkl[LL_*EDIM*EDIM];
__device__ __nv_bfloat16 g_Wvh[LL_*EDIM*EDIM], g_Wvl[LL_*EDIM*EDIM];
__device__ __nv_bfloat16 g_Woh[LL_*EDIM*EDIM], g_Wol[LL_*EDIM*EDIM];
__device__ __nv_bfloat16 g_W1h[LL_*EDIM*FF_],  g_W1l[LL_*EDIM*FF_];
__device__ __nv_bfloat16 g_W2h[LL_*EDIM*FF_],  g_W2l[LL_*EDIM*FF_];
__device__ __nv_bfloat16 g_Whh[EDIM*VV_],      g_Whl[EDIM*VV_];

// ---------------- PTX helpers (family-safe) ----------------
__device__ __forceinline__ uint32_t smem_u32(const void* p) {
    uint32_t a;
    asm("{ .reg .u64 t; cvta.to.shared.u64 t, %1; cvt.u32.u64 %0, t; }" : "=r"(a) : "l"(p));
    return a;
}
__device__ __forceinline__ void ldsm_x4(uint32_t* r, uint32_t addr) {
    asm volatile("ldmatrix.sync.aligned.m8n8.x4.shared.b16 {%0,%1,%2,%3}, [%4];"
                 : "=r"(r[0]), "=r"(r[1]), "=r"(r[2]), "=r"(r[3]) : "r"(addr));
}
__device__ __forceinline__ void ldsm_x4_t(uint32_t* r, uint32_t addr) {
    asm volatile("ldmatrix.sync.aligned.m8n8.x4.trans.shared.b16 {%0,%1,%2,%3}, [%4];"
                 : "=r"(r[0]), "=r"(r[1]), "=r"(r[2]), "=r"(r[3]) : "r"(addr));
}
__device__ __forceinline__ void mma16816(float* d, const uint32_t* a, const uint32_t* b) {
    asm volatile("mma.sync.aligned.m16n8k16.row.col.f32.bf16.bf16.f32 "
                 "{%0,%1,%2,%3}, {%4,%5,%6,%7}, {%8,%9}, {%0,%1,%2,%3};"
                 : "+f"(d[0]), "+f"(d[1]), "+f"(d[2]), "+f"(d[3])
                 : "r"(a[0]), "r"(a[1]), "r"(a[2]), "r"(a[3]), "r"(b[0]), "r"(b[1]));
}
#define CP_ASYNC16(dst, src) \
    asm volatile("cp.async.cg.shared.global [%0], [%1], 16;" :: "r"(dst), "l"(src))
#define CP_COMMIT() asm volatile("cp.async.commit_group;" ::: "memory")
#define CP_WAIT(n)  asm volatile("cp.async.wait_group %0;" :: "n"(n) : "memory")

__device__ __forceinline__ __nv_bfloat162 split_hi2(float a, float b) {
    __nv_bfloat162 r; r.x = __float2bfloat16(a); r.y = __float2bfloat16(b); return r;
}
__device__ __forceinline__ __nv_bfloat162 split_lo2(float a, float b,
                                                    __nv_bfloat162 h) {
    __nv_bfloat162 r;
    r.x = __float2bfloat16(a - __bfloat162float(h.x));
    r.y = __float2bfloat16(b - __bfloat162float(h.y));
    return r;
}

// ---------------- reductions ----------------
__device__ __forceinline__ float blockReduceSum(float v, float* sh) {
    __syncthreads();
    #pragma unroll
    for (int o = 16; o; o >>= 1) v += __shfl_xor_sync(0xffffffffu, v, o);
    if ((threadIdx.x & 31) == 0) sh[threadIdx.x >> 5] = v;
    __syncthreads();
    int nw = blockDim.x >> 5;
    float t = (threadIdx.x < (unsigned)nw) ? sh[threadIdx.x] : 0.f;
    if (threadIdx.x < 32) {
        #pragma unroll
        for (int o = 16; o; o >>= 1) t += __shfl_xor_sync(0xffffffffu, t, o);
        if (threadIdx.x == 0) sh[0] = t;
    }
    __syncthreads();
    return sh[0];
}

// ---------------- token dtype detect ----------------
__global__ void detect_kernel(const int* __restrict__ tok) {
    __shared__ int nz;
    if (threadIdx.x == 0) nz = 0;
    __syncthreads();
    int c = 0;
    for (int j = threadIdx.x; j < 1024; j += blockDim.x)
        if (tok[2*j + 1] != 0) c++;
    if (c) atomicAdd(&nz, c);
    __syncthreads();
    if (threadIdx.x == 0) g_tok64 = (nz == 0) ? 1 : 0;
}

// ---------------- embedding + positional encoding ----------------
__global__ __launch_bounds__(256) void embed_kernel(const void* __restrict__ tokp,
                                                    const float* __restrict__ emb,
                                                    float* __restrict__ X) {
    int row = blockIdx.x;
    int t   = row & (TT_ - 1);
    int token;
    if (g_tok64) token = (int)((const long long*)tokp)[row];
    else         token = ((const int*)tokp)[row];
    int e = threadIdx.x * 4;
    float4 v = *(const float4*)(emb + (size_t)token * EDIM + e);
    double i0 = (double)(e >> 1);
    double i1 = i0 + 1.0;
    double d0 = pow(10000.0, 2.0 * i0 / (double)EDIM);
    double d1 = pow(10000.0, 2.0 * i1 / (double)EDIM);
    double a0 = (double)t / d0;
    double a1 = (double)t / d1;
    v.x += (float)sin(a0); v.y += (float)cos(a0);
    v.z += (float)sin(a1); v.w += (float)cos(a1);
    *(float4*)(X + (size_t)row * EDIM + e) = v;
}

// ---------------- layernorm + bf16 split emit ----------------
__global__ __launch_bounds__(256) void ln_kernel(const float* __restrict__ X,
                                                 const float* __restrict__ g,
                                                 const float* __restrict__ b,
                                                 float* __restrict__ Y,
                                                 __nv_bfloat16* __restrict__ Oh,
                                                 __nv_bfloat16* __restrict__ Ol) {
    __shared__ float sh[32];
    int row = blockIdx.x;
    int e = threadIdx.x * 4;
    const float* xr = X + (size_t)row * EDIM;
    float4 v = *(const float4*)(xr + e);
    float mean = blockReduceSum(v.x + v.y + v.z + v.w, sh) * (1.f / EDIM);
    float dx = v.x - mean, dy = v.y - mean, dz = v.z - mean, dw = v.w - mean;
    float var = blockReduceSum(dx*dx + dy*dy + dz*dz + dw*dw, sh) * (1.f / EDIM);
    float r = rsqrtf(var + 1e-5f);
    float4 gg = *(const float4*)(g + e);
    float4 bb = *(const float4*)(b + e);
    float4 o;
    o.x = dx * r * gg.x + bb.x;
    o.y = dy * r * gg.y + bb.y;
    o.z = dz * r * gg.z + bb.z;
    o.w = dw * r * gg.w + bb.w;
    size_t base = (size_t)row * EDIM + e;
    *(float4*)(Y + base) = o;
    __nv_bfloat162 h0 = split_hi2(o.x, o.y), h1 = split_hi2(o.z, o.w);
    *(__nv_bfloat162*)(Oh + base)     = h0;
    *(__nv_bfloat162*)(Oh + base + 2) = h1;
    *(__nv_bfloat162*)(Ol + base)     = split_lo2(o.x, o.y, h0);
    *(__nv_bfloat162*)(Ol + base + 2) = split_lo2(o.z, o.w, h1);
}

// ---------------- fp32 -> bf16 hi/lo streaming split, 8 elems/thread --------
__global__ __launch_bounds__(256) void cvt_w_kernel(const float* __restrict__ W,
                                                    __nv_bfloat16* __restrict__ H,
                                                    __nv_bfloat16* __restrict__ Lo) {
    size_t i = ((size_t)blockIdx.x * 256 + threadIdx.x) * 8;
    float4 a0 = *(const float4*)(W + i);
    float4 a1 = *(const float4*)(W + i + 4);
    __nv_bfloat162 hb[4], lb[4];
    hb[0] = split_hi2(a0.x, a0.y); hb[1] = split_hi2(a0.z, a0.w);
    hb[2] = split_hi2(a1.x, a1.y); hb[3] = split_hi2(a1.z, a1.w);
    lb[0] = split_lo2(a0.x, a0.y, hb[0]); lb[1] = split_lo2(a0.z, a0.w, hb[1]);
    lb[2] = split_lo2(a1.x, a1.y, hb[2]); lb[3] = split_lo2(a1.z, a1.w, hb[3]);
    *(uint4*)(H + i)  = *(uint4*)hb;
    *(uint4*)(Lo + i) = *(uint4*)lb;
}

// ---------------- bf16 hi/lo tensor-core GEMM (mma.sync, 2-stage) -----------
// C[M,N] = A[M,K] @ B[K,N] ; fp32 accum of hh + hl + lh.
// A row-major [M,K]; B row-major [K,N] (natural weight layout, ldmatrix.trans).
// CTA tile 128x128, 8 warps 2(m)x4(n), warp 64x32, K chunk 32, 2 cp.async stages.
// 75776 B smem => 2 CTAs/SM => 16 warps/SM = 4 warps/SMSP (the proven invariant).
// Inner MMAs split into 3 passes (hh, hl, lh) -> acc RAW reuse distance 16.
#define ASTRIDE 40
#define BSTRIDE 136
#define A_TILE (128 * ASTRIDE)                // 5120 bf16
#define B_TILE (32 * BSTRIDE)                 // 4352 bf16
#define STAGE_ELEMS (2 * A_TILE + 2 * B_TILE) // 18944 bf16
#define NSTAGE 2
#define GEMM_SMEM (NSTAGE * STAGE_ELEMS * 2)  // 75776 B

__global__ __launch_bounds__(256, 2) void gemm_kernel(
    const __nv_bfloat16* __restrict__ Ah, const __nv_bfloat16* __restrict__ Al,
    const __nv_bfloat16* __restrict__ Bh0, const __nv_bfloat16* __restrict__ Bl0,
    const __nv_bfloat16* __restrict__ Bh1, const __nv_bfloat16* __restrict__ Bl1,
    const __nv_bfloat16* __restrict__ Bh2, const __nv_bfloat16* __restrict__ Bl2,
    float* __restrict__ C0, float* __restrict__ C1, float* __restrict__ C2,
    __nv_bfloat16* __restrict__ Oh, __nv_bfloat16* __restrict__ Ol,
    const float* __restrict__ bias, const float* __restrict__ res,
    int K, int N, int relu)
{
    extern __shared__ __nv_bfloat16 smem[];
    const int tid = threadIdx.x;
    const int lane = tid & 31, wid = tid >> 5;
    const int wm = wid & 1, wn = wid >> 1;
    const int bm = blockIdx.x * 128, bn = blockIdx.y * 128;
    const int z = blockIdx.z;
    const __nv_bfloat16* Bh = (z == 0) ? Bh0 : (z == 1) ? Bh1 : Bh2;
    const __nv_bfloat16* Bl = (z == 0) ? Bl0 : (z == 1) ? Bl1 : Bl2;
    float* C = (z == 0) ? C0 : (z == 1) ? C1 : C2;

    const uint32_t sb = smem_u32(smem);
    const int nc = K >> 5;

    const int a_row  = tid >> 2;
    const int a_cc   = (tid & 3) * 8;
    const int a_row2 = (tid + 256) >> 2;
    const int a_cc2  = ((tid + 256) & 3) * 8;
    const int b_row  = tid >> 4;               // 0..15
    const int b_cc   = (tid & 15) * 8;         // 0..120
    const int b_row2 = (tid + 256) >> 4;       // 16..31

    auto load_stage = [&](int st, int kc) {
        uint32_t base = sb + (uint32_t)(st * STAGE_ELEMS * 2);
        #pragma unroll
        for (int t4 = 0; t4 < 2; t4++) {
            const __nv_bfloat16* src = t4 ? Al : Ah;
            uint32_t dstb = base + (uint32_t)(t4 * A_TILE * 2);
            CP_ASYNC16(dstb + (a_row  * ASTRIDE + a_cc)  * 2,
                       src + (size_t)(bm + a_row)  * K + kc * 32 + a_cc);
            CP_ASYNC16(dstb + (a_row2 * ASTRIDE + a_cc2) * 2,
                       src + (size_t)(bm + a_row2) * K + kc * 32 + a_cc2);
        }
        #pragma unroll
        for (int t4 = 0; t4 < 2; t4++) {
            const __nv_bfloat16* src = t4 ? Bl : Bh;
            uint32_t dstb = base + (uint32_t)((2 * A_TILE + t4 * B_TILE) * 2);
            CP_ASYNC16(dstb + (b_row  * BSTRIDE + b_cc) * 2,
                       src + (size_t)(kc * 32 + b_row)  * N + bn + b_cc);
            CP_ASYNC16(dstb + (b_row2 * BSTRIDE + b_cc) * 2,
                       src + (size_t)(kc * 32 + b_row2) * N + bn + b_cc);
        }
    };

    float acc[4][4][4];
    #pragma unroll
    for (int i = 0; i < 4; i++)
        #pragma unroll
        for (int j = 0; j < 4; j++)
            #pragma unroll
            for (int r = 0; r < 4; r++) acc[i][j][r] = 0.f;

    load_stage(0, 0); CP_COMMIT();

    const int a_lrow = lane & 15;
    const int a_lcol = (lane & 16) ? 8 : 0;
    const int bt_row = lane & 15;
    const int bt_col = (lane >> 4) * 8;

    for (int c = 0; c < nc; c++) {
        CP_WAIT(0);
        __syncthreads();
        // Slot (c+1)&1 was last READ in iter c-1; all threads past this
        // barrier, so writing it now is race-free.
        if (c + 1 < nc) { load_stage((c + 1) & 1, c + 1); CP_COMMIT(); }

        const uint32_t stb = sb + (uint32_t)(((c & 1) * STAGE_ELEMS) * 2);
        const uint32_t pAh = stb;
        const uint32_t pAl = stb + A_TILE * 2;
        const uint32_t pBh = stb + 2 * A_TILE * 2;
        const uint32_t pBl = pBh + B_TILE * 2;

        #pragma unroll
        for (int ks = 0; ks < 2; ks++) {
            const int k0 = ks * 16;
            uint32_t ah[4][4], al[4][4];
            #pragma unroll
            for (int mf = 0; mf < 4; mf++) {
                int row = wm * 64 + mf * 16 + a_lrow;
                uint32_t off = (uint32_t)((row * ASTRIDE + k0 + a_lcol) * 2);
                ldsm_x4(ah[mf], pAh + off);
                ldsm_x4(al[mf], pAl + off);
            }
            uint32_t bh[2][4], bl[2][4];
            #pragma unroll
            for (int np = 0; np < 2; np++) {
                uint32_t off = (uint32_t)(((k0 + bt_row) * BSTRIDE
                                + wn * 32 + np * 16 + bt_col) * 2);
                ldsm_x4_t(bh[np], pBh + off);
                ldsm_x4_t(bl[np], pBl + off);
            }
            // pass 1: hh  (per-acc order hh -> hl -> lh preserved)
            #pragma unroll
            for (int mf = 0; mf < 4; mf++)
                #pragma unroll
                for (int np = 0; np < 2; np++)
                    #pragma unroll
                    for (int sub = 0; sub < 2; sub++)
                        mma16816(acc[mf][np * 2 + sub], ah[mf], &bh[np][2 * sub]);
            // pass 2: hl
            #pragma unroll
            for (int mf = 0; mf < 4; mf++)
                #pragma unroll
                for (int np = 0; np < 2; np++)
                    #pragma unroll
                    for (int sub = 0; sub < 2; sub++)
                        mma16816(acc[mf][np * 2 + sub], ah[mf], &bl[np][2 * sub]);
            // pass 3: lh
            #pragma unroll
            for (int mf = 0; mf < 4; mf++)
                #pragma unroll
                for (int np = 0; np < 2; np++)
                    #pragma unroll
                    for (int sub = 0; sub < 2; sub++)
                        mma16816(acc[mf][np * 2 + sub], al[mf], &bh[np][2 * sub]);
        }
    }
    __syncthreads();

    // epilogue
    #pragma unroll
    for (int mf = 0; mf < 4; mf++) {
        int row0 = bm + wm * 64 + mf * 16 + (lane >> 2);
        #pragma unroll
        for (int nf = 0; nf < 4; nf++) {
            int col = bn + wn * 32 + nf * 8 + (lane & 3) * 2;
            float2 bv = bias ? *(const float2*)(bias + col) : make_float2(0.f, 0.f);
            #pragma unroll
            for (int half = 0; half < 2; half++) {
                int row = row0 + half * 8;
                float v0 = acc[mf][nf][half * 2 + 0] + bv.x;
                float v1 = acc[mf][nf][half * 2 + 1] + bv.y;
                if (res) {
                    float2 rv = *(const float2*)(res + (size_t)row * N + col);
                    v0 += rv.x; v1 += rv.y;
                }
                if (relu) { v0 = fmaxf(v0, 0.f); v1 = fmaxf(v1, 0.f); }
                if (Oh) {
                    __nv_bfloat162 h = split_hi2(v0, v1);
                    *(__nv_bfloat162*)(Oh + (size_t)row * N + col) = h;
                    *(__nv_bfloat162*)(Ol + (size_t)row * N + col) = split_lo2(v0, v1, h);
                } else {
                    *(float2*)(C + (size_t)row * N + col) = make_float2(v0, v1);
                }
            }
        }
    }
}

// ---------------- fused flash attention (fp32 compute, bf16 split out) ------
#define FL_STRIDE 68
#define FL_SMEM   (3 * 64 * FL_STRIDE * 4)

__global__ __launch_bounds__(256) void flash_kernel(const float* __restrict__ Q,
                                                    const float* __restrict__ Km,
                                                    const float* __restrict__ V,
                                                    __nv_bfloat16* __restrict__ Oh,
                                                    __nv_bfloat16* __restrict__ Ol) {
    extern __shared__ float smf[];
    float (*Ks)[FL_STRIDE] = (float(*)[FL_STRIDE])smf;
    float (*Vs)[FL_STRIDE] = (float(*)[FL_STRIDE])(smf + 64 * FL_STRIDE);
    float (*QP)[FL_STRIDE] = (float(*)[FL_STRIDE])(smf + 2 * 64 * FL_STRIDE);

    const int bt = blockIdx.x;
    const int bh = blockIdx.y, b = bh / HH_, h = bh % HH_;
    const int tx = threadIdx.x, ty = threadIdx.y;
    const int tid = ty * 16 + tx;
    const int lr = tid >> 4;
    const int d4 = (tid & 15) * 4;

    #pragma unroll
    for (int rr = 0; rr < 4; rr++) {
        int r = lr + rr * 16;
        float4 kv = *(const float4*)(Km + (size_t)(b*TT_ + bt*64 + r) * EDIM + h*HD_ + d4);
        Ks[d4+0][r] = kv.x; Ks[d4+1][r] = kv.y; Ks[d4+2][r] = kv.z; Ks[d4+3][r] = kv.w;
    }

    float acc[4][4] = {};
    float m[4], l[4];
    #pragma unroll
    for (int i = 0; i < 4; i++) { m[i] = -1e30f; l[i] = 0.f; }
    const float scale = 0.125f;

    for (int st = 0; st <= bt; st++) {
        __syncthreads();
        #pragma unroll
        for (int rr = 0; rr < 4; rr++) {
            int r = lr + rr * 16;
            float4 qv = *(const float4*)(Q + (size_t)(b*TT_ + st*64 + r) * EDIM + h*HD_ + d4);
            QP[d4+0][r] = qv.x; QP[d4+1][r] = qv.y; QP[d4+2][r] = qv.z; QP[d4+3][r] = qv.w;
            float4 vv = *(const float4*)(V + (size_t)(b*TT_ + st*64 + r) * EDIM + h*HD_ + d4);
            *(float4*)&Vs[r][d4] = vv;
        }
        __syncthreads();

        float s4[4][4] = {};
        #pragma unroll
        for (int d = 0; d < 64; d++) {
            float4 a = *(float4*)&Ks[d][ty * 4];
            float4 q = *(float4*)&QP[d][tx * 4];
            float ar[4] = {a.x, a.y, a.z, a.w};
            float qr[4] = {q.x, q.y, q.z, q.w};
            #pragma unroll
            for (int i = 0; i < 4; i++)
                #pragma unroll
                for (int j = 0; j < 4; j++) s4[i][j] += ar[i] * qr[j];
        }
        if (st == bt) {
            #pragma unroll
            for (int i = 0; i < 4; i++)
                #pragma unroll
                for (int j = 0; j < 4; j++)
                    s4[i][j] = (tx*4+j <= ty*4+i) ? s4[i][j] * scale : -1e30f;
        } else {
            #pragma unroll
            for (int i = 0; i < 4; i++)
                #pragma unroll
                for (int j = 0; j < 4; j++) s4[i][j] *= scale;
        }

        __syncthreads();

        #pragma unroll
        for (int i = 0; i < 4; i++) {
            float mx = fmaxf(fmaxf(s4[i][0], s4[i][1]), fmaxf(s4[i][2], s4[i][3]));
            #pragma unroll
            for (int o = 8; o; o >>= 1) mx = fmaxf(mx, __shfl_xor_sync(0xffffffffu, mx, o, 16));
            float mn = fmaxf(m[i], mx);
            float alpha = __expf(m[i] - mn);
            float p0 = __expf(s4[i][0] - mn);
            float p1 = __expf(s4[i][1] - mn);
            float p2 = __expf(s4[i][2] - mn);
            float p3 = __expf(s4[i][3] - mn);
            float rs = p0 + p1 + p2 + p3;
            #pragma unroll
            for (int o = 8; o; o >>= 1) rs += __shfl_xor_sync(0xffffffffu, rs, o, 16);
            l[i] = l[i] * alpha + rs;
            m[i] = mn;
            #pragma unroll
            for (int j = 0; j < 4; j++) acc[i][j] *= alpha;
            QP[tx*4+0][ty*4+i] = p0;
            QP[tx*4+1][ty*4+i] = p1;
            QP[tx*4+2][ty*4+i] = p2;
            QP[tx*4+3][ty*4+i] = p3;
        }
        __syncthreads();

        #pragma unroll
        for (int s = 0; s < 64; s++) {
            float4 pv = *(float4*)&QP[s][ty * 4];
            float4 vv = *(float4*)&Vs[s][tx * 4];
            float pr[4] = {pv.x, pv.y, pv.z, pv.w};
            float vr[4] = {vv.x, vv.y, vv.z, vv.w};
            #pragma unroll
            for (int i = 0; i < 4; i++)
                #pragma unroll
                for (int j = 0; j < 4; j++) acc[i][j] += pr[i] * vr[j];
        }
    }

    #pragma unroll
    for (int i = 0; i < 4; i++) {
        float inv = 1.f / l[i];
        int tg = bt * 64 + ty * 4 + i;
        size_t base = (size_t)(b*TT_ + tg) * EDIM + h*HD_ + tx*4;
        float v0 = acc[i][0] * inv, v1 = acc[i][1] * inv;
        float v2 = acc[i][2] * inv, v3 = acc[i][3] * inv;
        __nv_bfloat162 h0 = split_hi2(v0, v1), h1 = split_hi2(v2, v3);
        *(__nv_bfloat162*)(Oh + base)     = h0;
        *(__nv_bfloat162*)(Oh + base + 2) = h1;
        *(__nv_bfloat162*)(Ol + base)     = split_lo2(v0, v1, h0);
        *(__nv_bfloat162*)(Ol + base + 2) = split_lo2(v2, v3, h1);
    }
}

// ---------------- host driver ----------------
template <typename T>
static T* symAddr(const void* sym) {
    void* p = nullptr;
    cudaGetSymbolAddress(&p, sym);
    return (T*)p;
}

extern "C" void kernel_launch(void* const* d_in, const int* in_sizes, int n_in,
                              void* d_out, int out_size) {
    const void*  tokens = d_in[0];
    const float* emb    = (const float*)d_in[1];
    const float* Wq     = (const float*)d_in[2];
    const float* Wk     = (const float*)d_in[3];
    const float* Wv     = (const float*)d_in[4];
    const float* Wo     = (const float*)d_in[5];
    const float* bo     = (const float*)d_in[6];
    const float* ln1_g  = (const float*)d_in[7];
    const float* ln1_b  = (const float*)d_in[8];
    const float* ln2_g  = (const float*)d_in[9];
    const float* ln2_b  = (const float*)d_in[10];
    const float* W1     = (const float*)d_in[11];
    const float* b1     = (const float*)d_in[12];
    const float* W2     = (const float*)d_in[13];
    const float* b2     = (const float*)d_in[14];
    const float* lnf_g  = (const float*)d_in[15];
    const float* lnf_b  = (const float*)d_in[16];
    const float* Wh     = (const float*)d_in[17];
    const float* bh     = (const float*)d_in[18];

    float* px  = symAddr<float>(g_x);
    float* pz  = symAddr<float>(g_z);
    float* pz2 = symAddr<float>(g_z2);
    float* pq  = symAddr<float>(g_q);
    float* pk  = symAddr<float>(g_k);
    float* pv  = symAddr<float>(g_v);
    __nv_bfloat16* pAh = symAddr<__nv_bfloat16>(g_Ah);
    __nv_bfloat16* pAl = symAddr<__nv_bfloat16>(g_Al);
    __nv_bfloat16* pHh = symAddr<__nv_bfloat16>(g_Hh);
    __nv_bfloat16* pHl = symAddr<__nv_bfloat16>(g_Hl);
    __nv_bfloat16* pWqh = symAddr<__nv_bfloat16>(g_Wqh), *pWql = symAddr<__nv_bfloat16>(g_Wql);
    __nv_bfloat16* pWkh = symAddr<__nv_bfloat16>(g_Wkh), *pWkl = symAddr<__nv_bfloat16>(g_Wkl);
    __nv_bfloat16* pWvh = symAddr<__nv_bfloat16>(g_Wvh), *pWvl = symAddr<__nv_bfloat16>(g_Wvl);
    __nv_bfloat16* pWoh = symAddr<__nv_bfloat16>(g_Woh), *pWol = symAddr<__nv_bfloat16>(g_Wol);
    __nv_bfloat16* pW1h = symAddr<__nv_bfloat16>(g_W1h), *pW1l = symAddr<__nv_bfloat16>(g_W1l);
    __nv_bfloat16* pW2h = symAddr<__nv_bfloat16>(g_W2h), *pW2l = symAddr<__nv_bfloat16>(g_W2l);
    __nv_bfloat16* pWhh = symAddr<__nv_bfloat16>(g_Whh), *pWhl = symAddr<__nv_bfloat16>(g_Whl);

    cudaFuncSetAttribute(flash_kernel, cudaFuncAttributeMaxDynamicSharedMemorySize, FL_SMEM);
    cudaFuncSetAttribute(gemm_kernel,  cudaFuncAttributeMaxDynamicSharedMemorySize, GEMM_SMEM);

    const size_t EE = (size_t)EDIM * EDIM;
    const size_t EF = (size_t)EDIM * FF_;

    // ---- weight conversion: 7 batched launches over full [L,...] tensors ---
    cvt_w_kernel<<<(int)(LL_*EE / 2048), 256>>>(Wq, pWqh, pWql);
    cvt_w_kernel<<<(int)(LL_*EE / 2048), 256>>>(Wk, pWkh, pWkl);
    cvt_w_kernel<<<(int)(LL_*EE / 2048), 256>>>(Wv, pWvh, pWvl);
    cvt_w_kernel<<<(int)(LL_*EE / 2048), 256>>>(Wo, pWoh, pWol);
    cvt_w_kernel<<<(int)(LL_*EF / 2048), 256>>>(W1, pW1h, pW1l);
    cvt_w_kernel<<<(int)(LL_*EF / 2048), 256>>>(W2, pW2h, pW2l);
    cvt_w_kernel<<<(int)((size_t)EDIM * VV_ / 2048), 256>>>(Wh, pWhh, pWhl);

    detect_kernel<<<1, 256>>>((const int*)tokens);
    embed_kernel<<<MROWS, 256>>>(tokens, emb, px);

    // grids: x = M tiles (fastest) for L2 B-reuse
    dim3 gQKV(MROWS/128, EDIM/128, 3);
    dim3 gEE(MROWS/128, EDIM/128, 1);
    dim3 gEF(MROWS/128, FF_/128, 1);
    dim3 gEV(MROWS/128, VV_/128, 1);
    dim3 thr2(16, 16);

    for (int l = 0; l < LL_; l++) {
        ln_kernel<<<MROWS, 256>>>(px, ln1_g + l*EDIM, ln1_b + l*EDIM, pz, pAh, pAl);
        gemm_kernel<<<gQKV, 256, GEMM_SMEM>>>(pAh, pAl,
            pWqh + l*EE, pWql + l*EE, pWkh + l*EE, pWkl + l*EE, pWvh + l*EE, pWvl + l*EE,
            pq, pk, pv, nullptr, nullptr, nullptr, nullptr, EDIM, EDIM, 0);
        flash_kernel<<<dim3(TT_/64, BHN), thr2, FL_SMEM>>>(pq, pk, pv, pAh, pAl);
        gemm_kernel<<<gEE, 256, GEMM_SMEM>>>(pAh, pAl,
            pWoh + l*EE, pWol + l*EE, nullptr, nullptr, nullptr, nullptr,
            pz, nullptr, nullptr, nullptr, nullptr, bo + l*EDIM, pz, EDIM, EDIM, 0);
        ln_kernel<<<MROWS, 256>>>(pz, ln2_g + l*EDIM, ln2_b + l*EDIM, pz2, pAh, pAl);
        gemm_kernel<<<gEF, 256, GEMM_SMEM>>>(pAh, pAl,
            pW1h + l*EF, pW1l + l*EF, nullptr, nullptr, nullptr, nullptr,
            nullptr, nullptr, nullptr, pHh, pHl, b1 + l*FF_, nullptr, EDIM, FF_, 1);
        gemm_kernel<<<gEE, 256, GEMM_SMEM>>>(pHh, pHl,
            pW2h + l*EF, pW2l + l*EF, nullptr, nullptr, nullptr, nullptr,
            px, nullptr, nullptr, nullptr, nullptr, b2 + l*EDIM, pz2, FF_, EDIM, 0);
    }
    ln_kernel<<<MROWS, 256>>>(px, lnf_g, lnf_b, pz, pAh, pAl);
    gemm_kernel<<<gEV, 256, GEMM_SMEM>>>(pAh, pAl,
        pWhh, pWhl, nullptr, nullptr, nullptr, nullptr,
        (float*)d_out, nullptr, nullptr, nullptr, nullptr, bh, nullptr, EDIM, VV_, 0);
}